// round 1
// baseline (speedup 1.0000x reference)
#include <cuda_runtime.h>

#define N_NODES 50000
#define N_EDGES 800000
#define D 128
#define R 4
#define NSEG (N_NODES * R)      // 200000
#define NLAYER 3
#define KTOT 640                // R*D + D
#define NKC 40                  // KTOT / 16

// ---------------- static device scratch (no allocations allowed) ----------------
__device__ float g_s[(size_t)N_NODES * R * D];   // aggregated features [N, R*D]
__device__ float g_tmp[(size_t)N_NODES * D];     // GEMM output before epilogue
__device__ float g_x1[(size_t)N_NODES * D];      // ping-pong layer activations
__device__ float g_x2[(size_t)N_NODES * D];
__device__ int   g_cnt[NSEG];
__device__ int   g_off[NSEG + 1];
__device__ int   g_cursor[NSEG];
__device__ int   g_bsum[256];
__device__ int   g_srcs[N_EDGES];

// ---------------- CSR build: histogram + scan + scatter ----------------
__global__ void k_zero_cnt() {
    int i = blockIdx.x * blockDim.x + threadIdx.x;
    if (i < NSEG) g_cnt[i] = 0;
}

__global__ void k_hist(const int* __restrict__ dst, const int* __restrict__ et) {
    int e = blockIdx.x * blockDim.x + threadIdx.x;
    if (e < N_EDGES) atomicAdd(&g_cnt[dst[e] * R + et[e]], 1);
}

__global__ void k_scan1() {
    __shared__ int sh[1024];
    int t = threadIdx.x;
    int i = blockIdx.x * 1024 + t;
    int v = (i < NSEG) ? g_cnt[i] : 0;
    sh[t] = v;
    __syncthreads();
    for (int d = 1; d < 1024; d <<= 1) {
        int add = (t >= d) ? sh[t - d] : 0;
        __syncthreads();
        sh[t] += add;
        __syncthreads();
    }
    if (i < NSEG) g_off[i] = sh[t] - v;           // exclusive within block
    if (t == 1023) g_bsum[blockIdx.x] = sh[1023]; // block total
}

__global__ void k_scan2(int nb) {
    __shared__ int sh[256];
    int t = threadIdx.x;
    int v = (t < nb) ? g_bsum[t] : 0;
    sh[t] = v;
    __syncthreads();
    for (int d = 1; d < 256; d <<= 1) {
        int add = (t >= d) ? sh[t - d] : 0;
        __syncthreads();
        sh[t] += add;
        __syncthreads();
    }
    if (t < nb) g_bsum[t] = sh[t] - v;            // exclusive block offsets
}

__global__ void k_scan3() {
    int t = threadIdx.x;
    int i = blockIdx.x * 1024 + t;
    if (i < NSEG) {
        int o = g_off[i] + g_bsum[blockIdx.x];
        g_off[i] = o;
        g_cursor[i] = o;
    }
    if (i == 0) g_off[NSEG] = N_EDGES;
}

__global__ void k_scatter(const int* __restrict__ src, const int* __restrict__ dst,
                          const int* __restrict__ et) {
    int e = blockIdx.x * blockDim.x + threadIdx.x;
    if (e < N_EDGES) {
        int seg = dst[e] * R + et[e];
        int pos = atomicAdd(&g_cursor[seg], 1);
        g_srcs[pos] = src[e];
    }
}

// ---------------- per-layer: segment-mean aggregation (warp per segment) ----------------
__global__ void k_agg(const float* __restrict__ x) {
    int seg = blockIdx.x * 8 + (threadIdx.x >> 5);
    if (seg >= NSEG) return;
    int lane = threadIdx.x & 31;
    int beg = g_off[seg];
    int end = g_off[seg + 1];
    float ax = 0.f, ay = 0.f, az = 0.f, aw = 0.f;
    for (int j = beg; j < end; j++) {
        int sn = g_srcs[j];
        float4 v = *reinterpret_cast<const float4*>(x + (size_t)sn * D + lane * 4);
        ax += v.x; ay += v.y; az += v.z; aw += v.w;
    }
    float inv = (end > beg) ? 1.0f / (float)(end - beg) : 0.0f;
    float4 o;
    o.x = ax * inv; o.y = ay * inv; o.z = az * inv; o.w = aw * inv;
    *reinterpret_cast<float4*>(g_s + (size_t)seg * D + lane * 4) = o;
}

// ---------------- fused GEMM: [s | x] (N x 640) @ [W_l ; root_l] (640 x 128) + bias ----------------
__device__ __forceinline__ float4 ldA(const float* __restrict__ xin, int grow, int kc, int a_k4) {
    if (grow >= N_NODES) return make_float4(0.f, 0.f, 0.f, 0.f);
    if (kc < 32)
        return *reinterpret_cast<const float4*>(g_s + (size_t)grow * 512 + kc * 16 + a_k4);
    return *reinterpret_cast<const float4*>(xin + (size_t)grow * 128 + (kc - 32) * 16 + a_k4);
}

__global__ __launch_bounds__(256, 2) void k_gemm(const float* __restrict__ xin,
                                                 const float* __restrict__ W,
                                                 const float* __restrict__ Wroot,
                                                 const float* __restrict__ bias) {
    __shared__ float As[16][132];   // k-major A tile, padded for alignment
    __shared__ float Bs[16][128];

    int tid = threadIdx.x;
    int tx = tid & 15, ty = tid >> 4;
    int brow = blockIdx.x * 128;

    int a_row = tid >> 2;           // 0..63 (also handles a_row+64)
    int a_k4 = (tid & 3) * 4;       // 0,4,8,12
    int b_k0 = tid >> 5;            // 0..7 (also b_k0+8)
    int b_c4 = (tid & 31) * 4;      // 0..124

    float acc[8][8];
#pragma unroll
    for (int i = 0; i < 8; i++)
#pragma unroll
        for (int j = 0; j < 8; j++) acc[i][j] = 0.f;

    // prefetch chunk 0
    float4 pa0 = ldA(xin, brow + a_row, 0, a_k4);
    float4 pa1 = ldA(xin, brow + a_row + 64, 0, a_k4);
    const float* bp0 = W;   // kc=0
    float4 pb0 = *reinterpret_cast<const float4*>(bp0 + (size_t)b_k0 * 128 + b_c4);
    float4 pb1 = *reinterpret_cast<const float4*>(bp0 + (size_t)(b_k0 + 8) * 128 + b_c4);

    for (int kc = 0; kc < NKC; kc++) {
        // store prefetched tiles to smem
        As[a_k4 + 0][a_row] = pa0.x;
        As[a_k4 + 1][a_row] = pa0.y;
        As[a_k4 + 2][a_row] = pa0.z;
        As[a_k4 + 3][a_row] = pa0.w;
        As[a_k4 + 0][a_row + 64] = pa1.x;
        As[a_k4 + 1][a_row + 64] = pa1.y;
        As[a_k4 + 2][a_row + 64] = pa1.z;
        As[a_k4 + 3][a_row + 64] = pa1.w;
        *reinterpret_cast<float4*>(&Bs[b_k0][b_c4]) = pb0;
        *reinterpret_cast<float4*>(&Bs[b_k0 + 8][b_c4]) = pb1;
        __syncthreads();

        if (kc + 1 < NKC) {
            int kn = kc + 1;
            pa0 = ldA(xin, brow + a_row, kn, a_k4);
            pa1 = ldA(xin, brow + a_row + 64, kn, a_k4);
            const float* bp = (kn < 32) ? (W + (size_t)kn * 16 * 128)
                                        : (Wroot + (size_t)(kn - 32) * 16 * 128);
            pb0 = *reinterpret_cast<const float4*>(bp + (size_t)b_k0 * 128 + b_c4);
            pb1 = *reinterpret_cast<const float4*>(bp + (size_t)(b_k0 + 8) * 128 + b_c4);
        }

#pragma unroll
        for (int k = 0; k < 16; k++) {
            float4 a0 = *reinterpret_cast<const float4*>(&As[k][ty * 4]);
            float4 a1 = *reinterpret_cast<const float4*>(&As[k][64 + ty * 4]);
            float4 b0 = *reinterpret_cast<const float4*>(&Bs[k][tx * 4]);
            float4 b1 = *reinterpret_cast<const float4*>(&Bs[k][64 + tx * 4]);
            float a[8] = {a0.x, a0.y, a0.z, a0.w, a1.x, a1.y, a1.z, a1.w};
            float b[8] = {b0.x, b0.y, b0.z, b0.w, b1.x, b1.y, b1.z, b1.w};
#pragma unroll
            for (int i = 0; i < 8; i++)
#pragma unroll
                for (int j = 0; j < 8; j++) acc[i][j] = fmaf(a[i], b[j], acc[i][j]);
        }
        __syncthreads();
    }

    // epilogue: + bias, write to g_tmp
    int c0 = tx * 4, c1 = 64 + tx * 4;
    float4 bv0 = *reinterpret_cast<const float4*>(bias + c0);
    float4 bv1 = *reinterpret_cast<const float4*>(bias + c1);
#pragma unroll
    for (int i = 0; i < 8; i++) {
        int row = (i < 4) ? (brow + ty * 4 + i) : (brow + 64 + ty * 4 + i - 4);
        if (row < N_NODES) {
            float4 o0, o1;
            o0.x = acc[i][0] + bv0.x; o0.y = acc[i][1] + bv0.y;
            o0.z = acc[i][2] + bv0.z; o0.w = acc[i][3] + bv0.w;
            o1.x = acc[i][4] + bv1.x; o1.y = acc[i][5] + bv1.y;
            o1.z = acc[i][6] + bv1.z; o1.w = acc[i][7] + bv1.w;
            *reinterpret_cast<float4*>(g_tmp + (size_t)row * 128 + c0) = o0;
            *reinterpret_cast<float4*>(g_tmp + (size_t)row * 128 + c1) = o1;
        }
    }
}

// ---------------- epilogue: relu + residual + layernorm (warp per row) ----------------
__global__ void k_epi(const float* __restrict__ xin, const float* __restrict__ gamma,
                      const float* __restrict__ beta, float* __restrict__ xout) {
    int row = blockIdx.x * 8 + (threadIdx.x >> 5);
    if (row >= N_NODES) return;
    int lane = threadIdx.x & 31;
    float4 t = *reinterpret_cast<const float4*>(g_tmp + (size_t)row * D + lane * 4);
    float4 xr = *reinterpret_cast<const float4*>(xin + (size_t)row * D + lane * 4);
    float4 v;
    v.x = fmaxf(t.x, 0.f) + xr.x;
    v.y = fmaxf(t.y, 0.f) + xr.y;
    v.z = fmaxf(t.z, 0.f) + xr.z;
    v.w = fmaxf(t.w, 0.f) + xr.w;
    float s = v.x + v.y + v.z + v.w;
    float sq = v.x * v.x + v.y * v.y + v.z * v.z + v.w * v.w;
#pragma unroll
    for (int o = 16; o; o >>= 1) {
        s += __shfl_xor_sync(0xFFFFFFFFu, s, o);
        sq += __shfl_xor_sync(0xFFFFFFFFu, sq, o);
    }
    float mean = s * (1.0f / 128.0f);
    float var = sq * (1.0f / 128.0f) - mean * mean;
    float rs = rsqrtf(var + 1e-5f);
    float4 g = *reinterpret_cast<const float4*>(gamma + lane * 4);
    float4 b = *reinterpret_cast<const float4*>(beta + lane * 4);
    float4 o;
    o.x = (v.x - mean) * rs * g.x + b.x;
    o.y = (v.y - mean) * rs * g.y + b.y;
    o.z = (v.z - mean) * rs * g.z + b.z;
    o.w = (v.w - mean) * rs * g.w + b.w;
    *reinterpret_cast<float4*>(xout + (size_t)row * D + lane * 4) = o;
}

// ---------------- host launcher (graph-capturable: kernels only) ----------------
extern "C" void kernel_launch(void* const* d_in, const int* in_sizes, int n_in,
                              void* d_out, int out_size) {
    const float* x     = (const float*)d_in[0];
    const int*   ei    = (const int*)d_in[1];
    const int*   et    = (const int*)d_in[2];
    const float* W     = (const float*)d_in[3];   // [L, R, D, D]
    const float* root  = (const float*)d_in[4];   // [L, D, D]
    const float* bias  = (const float*)d_in[5];   // [L, D]
    const float* gamma = (const float*)d_in[6];   // [L, D]
    const float* beta  = (const float*)d_in[7];   // [L, D]
    float* out = (float*)d_out;

    const int* src = ei;
    const int* dst = ei + N_EDGES;

    float *px1 = nullptr, *px2 = nullptr;
    cudaGetSymbolAddress((void**)&px1, g_x1);
    cudaGetSymbolAddress((void**)&px2, g_x2);

    // build CSR by (dst, relation) segment — edge structure is layer-invariant
    k_zero_cnt<<<(NSEG + 255) / 256, 256>>>();
    k_hist<<<(N_EDGES + 255) / 256, 256>>>(dst, et);
    int nb = (NSEG + 1023) / 1024;   // 196
    k_scan1<<<nb, 1024>>>();
    k_scan2<<<1, 256>>>(nb);
    k_scan3<<<nb, 1024>>>();
    k_scatter<<<(N_EDGES + 255) / 256, 256>>>(src, dst, et);

    const float* xin = x;
    for (int l = 0; l < NLAYER; l++) {
        k_agg<<<(NSEG + 7) / 8, 256>>>(xin);
        k_gemm<<<(N_NODES + 127) / 128, 256>>>(xin,
                                               W + (size_t)l * R * D * D,
                                               root + (size_t)l * D * D,
                                               bias + (size_t)l * D);
        float* xout = (l == NLAYER - 1) ? out : ((l == 0) ? px1 : px2);
        k_epi<<<(N_NODES + 7) / 8, 256>>>(xin, gamma + (size_t)l * D,
                                          beta + (size_t)l * D, xout);
        xin = xout;
    }
}

// round 3
// speedup vs baseline: 1.5145x; 1.5145x over previous
#include <cuda_runtime.h>
#include <cuda_bf16.h>
#include <cstdint>

#define N_NODES 50000
#define N_EDGES 800000
#define D 128
#define R 4
#define NSEG (N_NODES * R)      // 200000
#define NLAYER 3
#define KTOT 640                // R*D + D
#define MPAD 50048              // 391 * 128
#define NTILES 391
#define NCHUNK 10               // K chunks of 64 bf16 (128B rows)

// ---------------- static device scratch ----------------
__device__ __align__(16) __nv_bfloat16 g_ah[(size_t)MPAD * KTOT];  // A hi  [node][640]
__device__ __align__(16) __nv_bfloat16 g_al[(size_t)MPAD * KTOT];  // A lo
__device__ __align__(16) __nv_bfloat16 g_bh[(size_t)NLAYER * D * KTOT]; // B hi [l][n][k]
__device__ __align__(16) __nv_bfloat16 g_bl[(size_t)NLAYER * D * KTOT]; // B lo
__device__ float g_tmp[(size_t)N_NODES * D];
__device__ float g_x1[(size_t)N_NODES * D];
__device__ float g_x2[(size_t)N_NODES * D];
__device__ int   g_cnt[NSEG];
__device__ int   g_off[NSEG + 1];
__device__ int   g_cursor[NSEG];
__device__ int   g_bsum[256];
__device__ int   g_srcs[N_EDGES];

// ---------------- helpers ----------------
__device__ __forceinline__ uint32_t smem_to_u32(const void* p) {
    uint32_t a;
    asm("{ .reg .u64 t; cvta.to.shared.u64 t, %1; cvt.u32.u64 %0, t; }"
        : "=r"(a) : "l"(p));
    return a;
}

#define CP16(sm, gp) \
    asm volatile("cp.async.cg.shared.global [%0], [%1], 16;" :: "r"(sm), "l"(gp))

__device__ __forceinline__ void ldsm_x4(uint32_t* f, uint32_t addr) {
    asm volatile("ldmatrix.sync.aligned.m8n8.x4.shared.b16 {%0,%1,%2,%3}, [%4];"
                 : "=r"(f[0]), "=r"(f[1]), "=r"(f[2]), "=r"(f[3]) : "r"(addr));
}

__device__ __forceinline__ void mma16816(float* d, const uint32_t* a,
                                         uint32_t b0, uint32_t b1) {
    asm volatile(
        "mma.sync.aligned.m16n8k16.row.col.f32.bf16.bf16.f32 "
        "{%0,%1,%2,%3}, {%4,%5,%6,%7}, {%8,%9}, {%0,%1,%2,%3};"
        : "+f"(d[0]), "+f"(d[1]), "+f"(d[2]), "+f"(d[3])
        : "r"(a[0]), "r"(a[1]), "r"(a[2]), "r"(a[3]), "r"(b0), "r"(b1));
}

// ---------------- CSR build ----------------
__global__ void k_zero_cnt() {
    int i = blockIdx.x * blockDim.x + threadIdx.x;
    if (i < NSEG) g_cnt[i] = 0;
}

__global__ void k_hist(const int* __restrict__ dst, const int* __restrict__ et) {
    int e = blockIdx.x * blockDim.x + threadIdx.x;
    if (e < N_EDGES) atomicAdd(&g_cnt[dst[e] * R + et[e]], 1);
}

__global__ void k_scan1() {
    __shared__ int sh[1024];
    int t = threadIdx.x;
    int i = blockIdx.x * 1024 + t;
    int v = (i < NSEG) ? g_cnt[i] : 0;
    sh[t] = v;
    __syncthreads();
    for (int d = 1; d < 1024; d <<= 1) {
        int add = (t >= d) ? sh[t - d] : 0;
        __syncthreads();
        sh[t] += add;
        __syncthreads();
    }
    if (i < NSEG) g_off[i] = sh[t] - v;
    if (t == 1023) g_bsum[blockIdx.x] = sh[1023];
}

__global__ void k_scan2(int nb) {
    __shared__ int sh[256];
    int t = threadIdx.x;
    int v = (t < nb) ? g_bsum[t] : 0;
    sh[t] = v;
    __syncthreads();
    for (int d = 1; d < 256; d <<= 1) {
        int add = (t >= d) ? sh[t - d] : 0;
        __syncthreads();
        sh[t] += add;
        __syncthreads();
    }
    if (t < nb) g_bsum[t] = sh[t] - v;
}

__global__ void k_scan3() {
    int t = threadIdx.x;
    int i = blockIdx.x * 1024 + t;
    if (i < NSEG) {
        int o = g_off[i] + g_bsum[blockIdx.x];
        g_off[i] = o;
        g_cursor[i] = o;
    }
    if (i == 0) g_off[NSEG] = N_EDGES;
}

__global__ void k_scatter(const int* __restrict__ src, const int* __restrict__ dst,
                          const int* __restrict__ et) {
    int e = blockIdx.x * blockDim.x + threadIdx.x;
    if (e < N_EDGES) {
        int seg = dst[e] * R + et[e];
        int pos = atomicAdd(&g_cursor[seg], 1);
        g_srcs[pos] = src[e];
    }
}

// ---------------- weight prep: transpose + bf16 split ----------------
__global__ void k_bprep(const float* __restrict__ W, const float* __restrict__ root) {
    int i = blockIdx.x * 256 + threadIdx.x;     // over NLAYER*D*KTOT
    if (i >= NLAYER * D * KTOT) return;
    int k = i % KTOT;
    int t = i / KTOT;
    int n = t % D;
    int l = t / D;
    float w;
    if (k < 512) {
        int r = k >> 7, din = k & 127;
        w = W[(((size_t)l * R + r) * D + din) * D + n];
    } else {
        w = root[((size_t)l * D + (k - 512)) * D + n];
    }
    __nv_bfloat16 h = __float2bfloat16(w);
    float lo = w - __bfloat162float(h);
    g_bh[i] = h;
    g_bl[i] = __float2bfloat16(lo);
}

// ---------------- fill self-columns (512..639) of A from fp32 activations ----------------
__global__ void k_convx(const float* __restrict__ x) {
    int row = blockIdx.x * 8 + (threadIdx.x >> 5);
    if (row >= N_NODES) return;
    int lane = threadIdx.x & 31;
    float4 v = *reinterpret_cast<const float4*>(x + (size_t)row * D + lane * 4);
    __nv_bfloat16 h[4], lo[4];
    float vv[4] = {v.x, v.y, v.z, v.w};
#pragma unroll
    for (int j = 0; j < 4; j++) {
        h[j] = __float2bfloat16(vv[j]);
        lo[j] = __float2bfloat16(vv[j] - __bfloat162float(h[j]));
    }
    size_t o = (size_t)row * KTOT + 512 + lane * 4;
    *reinterpret_cast<uint2*>(&g_ah[o]) = *reinterpret_cast<uint2*>(h);
    *reinterpret_cast<uint2*>(&g_al[o]) = *reinterpret_cast<uint2*>(lo);
}

// ---------------- segment-mean aggregation -> bf16 hi/lo cols 0..511 ----------------
__global__ void k_agg(const float* __restrict__ x) {
    int seg = blockIdx.x * 8 + (threadIdx.x >> 5);
    if (seg >= NSEG) return;
    int lane = threadIdx.x & 31;
    int beg = g_off[seg];
    int end = g_off[seg + 1];
    float ax = 0.f, ay = 0.f, az = 0.f, aw = 0.f;
    for (int j = beg; j < end; j++) {
        int sn = g_srcs[j];
        float4 v = *reinterpret_cast<const float4*>(x + (size_t)sn * D + lane * 4);
        ax += v.x; ay += v.y; az += v.z; aw += v.w;
    }
    float inv = (end > beg) ? 1.0f / (float)(end - beg) : 0.0f;
    float vv[4] = {ax * inv, ay * inv, az * inv, aw * inv};
    __nv_bfloat16 h[4], lo[4];
#pragma unroll
    for (int j = 0; j < 4; j++) {
        h[j] = __float2bfloat16(vv[j]);
        lo[j] = __float2bfloat16(vv[j] - __bfloat162float(h[j]));
    }
    int node = seg >> 2;
    int r = seg & 3;
    size_t o = (size_t)node * KTOT + r * 128 + lane * 4;
    *reinterpret_cast<uint2*>(&g_ah[o]) = *reinterpret_cast<uint2*>(h);
    *reinterpret_cast<uint2*>(&g_al[o]) = *reinterpret_cast<uint2*>(lo);
}

// ---------------- HMMA GEMM: [A | selfA] @ [Wcat ; root]^T, 3-term bf16 split ----------------
// smem: [0:512) bias, tiles at 1024 + buf*65536: Ah(16K) Al(16K) Bh(16K) Bl(16K)
#define SMEM_DYN (1024 + 2 * 65536)

__global__ void __launch_bounds__(256) k_gemm(int layer, const float* __restrict__ bias) {
    extern __shared__ char smem[];
    float* sBias = (float*)smem;
    uint32_t smem_u = smem_to_u32(smem);
    int tid = threadIdx.x;
    int wid = tid >> 5;
    int lane = tid & 31;
    int brow = blockIdx.x * 128;

    if (tid < 32) {
        float4 b = *reinterpret_cast<const float4*>(bias + tid * 4);
        *reinterpret_cast<float4*>(&sBias[tid * 4]) = b;
    }

    const __nv_bfloat16* bh = g_bh + (size_t)layer * D * KTOT;
    const __nv_bfloat16* bl = g_bl + (size_t)layer * D * KTOT;

    // warp tile: 32 (m) x 64 (n)
    int wm = wid & 3;            // m0 = wm*32
    int wn = wid >> 2;           // n0 = wn*64
    int lrow = lane & 15;        // ldmatrix row within 16-row tile
    int kh16 = (lane >> 4) * 16; // k-half byte offset

    float acc[2][8][4];
#pragma unroll
    for (int t = 0; t < 2; t++)
#pragma unroll
        for (int q = 0; q < 8; q++)
#pragma unroll
            for (int j = 0; j < 4; j++) acc[t][q][j] = 0.f;

    // ---- cp.async tile loader ----
    auto load_chunk = [&](int c, int buf) {
        uint32_t base = smem_u + 1024 + buf * 65536;
        int kcol = c * 64;
#pragma unroll
        for (int it = 0; it < 4; it++) {
            int u = tid + it * 256;          // 0..1023
            int row = u >> 3;                // 0..127
            int c16 = u & 7;                 // 16B unit within 128B row
            uint32_t off = row * 128 + c16 * 16;
            uint32_t sw = off ^ ((off >> 3) & 0x70);
            const __nv_bfloat16* pa  = &g_ah[(size_t)(brow + row) * KTOT + kcol + c16 * 8];
            const __nv_bfloat16* pal = &g_al[(size_t)(brow + row) * KTOT + kcol + c16 * 8];
            const __nv_bfloat16* pb  = &bh[(size_t)row * KTOT + kcol + c16 * 8];
            const __nv_bfloat16* pbl = &bl[(size_t)row * KTOT + kcol + c16 * 8];
            CP16(base + sw, pa);
            CP16(base + 16384 + sw, pal);
            CP16(base + 32768 + sw, pb);
            CP16(base + 49152 + sw, pbl);
        }
        asm volatile("cp.async.commit_group;" ::: "memory");
    };

    load_chunk(0, 0);

    for (int c = 0; c < NCHUNK; c++) {
        if (c + 1 < NCHUNK) {
            load_chunk(c + 1, (c + 1) & 1);
            asm volatile("cp.async.wait_group 1;" ::: "memory");
        } else {
            asm volatile("cp.async.wait_group 0;" ::: "memory");
        }
        __syncthreads();

        uint32_t base = smem_u + 1024 + (c & 1) * 65536;
#pragma unroll
        for (int ks = 0; ks < 4; ks++) {
            int kb = ks * 32 + kh16;   // byte offset of k within chunk row
            // ---- load Ah (2 m-tiles) and Bh (4 n16-tiles) fragments ----
            uint32_t ah[2][4], al[2][4], bhf[4][4], blf[4][4];
#pragma unroll
            for (int t = 0; t < 2; t++) {
                int row = wm * 32 + t * 16 + lrow;
                uint32_t off = row * 128 + kb;
                ldsm_x4(ah[t], base + (off ^ ((off >> 3) & 0x70)));
            }
#pragma unroll
            for (int p = 0; p < 4; p++) {
                int row = wn * 64 + p * 16 + lrow;
                uint32_t off = row * 128 + kb;
                ldsm_x4(bhf[p], base + 32768 + (off ^ ((off >> 3) & 0x70)));
            }
            // pass 0: Ah * Bh
#pragma unroll
            for (int t = 0; t < 2; t++)
#pragma unroll
                for (int p = 0; p < 4; p++) {
                    mma16816(acc[t][2 * p + 0], ah[t], bhf[p][0], bhf[p][2]);
                    mma16816(acc[t][2 * p + 1], ah[t], bhf[p][1], bhf[p][3]);
                }
            // pass 1: Al * Bh
#pragma unroll
            for (int t = 0; t < 2; t++) {
                int row = wm * 32 + t * 16 + lrow;
                uint32_t off = row * 128 + kb;
                ldsm_x4(al[t], base + 16384 + (off ^ ((off >> 3) & 0x70)));
            }
#pragma unroll
            for (int t = 0; t < 2; t++)
#pragma unroll
                for (int p = 0; p < 4; p++) {
                    mma16816(acc[t][2 * p + 0], al[t], bhf[p][0], bhf[p][2]);
                    mma16816(acc[t][2 * p + 1], al[t], bhf[p][1], bhf[p][3]);
                }
            // pass 2: Ah * Bl
#pragma unroll
            for (int p = 0; p < 4; p++) {
                int row = wn * 64 + p * 16 + lrow;
                uint32_t off = row * 128 + kb;
                ldsm_x4(blf[p], base + 49152 + (off ^ ((off >> 3) & 0x70)));
            }
#pragma unroll
            for (int t = 0; t < 2; t++)
#pragma unroll
                for (int p = 0; p < 4; p++) {
                    mma16816(acc[t][2 * p + 0], ah[t], blf[p][0], blf[p][2]);
                    mma16816(acc[t][2 * p + 1], ah[t], blf[p][1], blf[p][3]);
                }
        }
        __syncthreads();
    }

    // ---- epilogue: + bias -> g_tmp ----
#pragma unroll
    for (int t = 0; t < 2; t++) {
        int mrow = brow + wm * 32 + t * 16 + (lane >> 2);
#pragma unroll
        for (int q = 0; q < 8; q++) {
            int col = wn * 64 + (q >> 1) * 16 + (q & 1) * 8 + 2 * (lane & 3);
            float bx = sBias[col], by = sBias[col + 1];
            if (mrow < N_NODES) {
                float2 o0 = make_float2(acc[t][q][0] + bx, acc[t][q][1] + by);
                *reinterpret_cast<float2*>(g_tmp + (size_t)mrow * D + col) = o0;
            }
            if (mrow + 8 < N_NODES) {
                float2 o1 = make_float2(acc[t][q][2] + bx, acc[t][q][3] + by);
                *reinterpret_cast<float2*>(g_tmp + (size_t)(mrow + 8) * D + col) = o1;
            }
        }
    }
}

// ---------------- epilogue: relu + residual + layernorm (+ bf16 self-cols) ----------------
__global__ void k_epi(const float* __restrict__ xin, const float* __restrict__ gamma,
                      const float* __restrict__ beta, float* __restrict__ xout,
                      int write_next) {
    int row = blockIdx.x * 8 + (threadIdx.x >> 5);
    if (row >= N_NODES) return;
    int lane = threadIdx.x & 31;
    float4 t = *reinterpret_cast<const float4*>(g_tmp + (size_t)row * D + lane * 4);
    float4 xr = *reinterpret_cast<const float4*>(xin + (size_t)row * D + lane * 4);
    float4 v;
    v.x = fmaxf(t.x, 0.f) + xr.x;
    v.y = fmaxf(t.y, 0.f) + xr.y;
    v.z = fmaxf(t.z, 0.f) + xr.z;
    v.w = fmaxf(t.w, 0.f) + xr.w;
    float s = v.x + v.y + v.z + v.w;
    float sq = v.x * v.x + v.y * v.y + v.z * v.z + v.w * v.w;
#pragma unroll
    for (int o = 16; o; o >>= 1) {
        s += __shfl_xor_sync(0xFFFFFFFFu, s, o);
        sq += __shfl_xor_sync(0xFFFFFFFFu, sq, o);
    }
    float mean = s * (1.0f / 128.0f);
    float var = sq * (1.0f / 128.0f) - mean * mean;
    float rs = rsqrtf(var + 1e-5f);
    float4 g = *reinterpret_cast<const float4*>(gamma + lane * 4);
    float4 b = *reinterpret_cast<const float4*>(beta + lane * 4);
    float4 o;
    o.x = (v.x - mean) * rs * g.x + b.x;
    o.y = (v.y - mean) * rs * g.y + b.y;
    o.z = (v.z - mean) * rs * g.z + b.z;
    o.w = (v.w - mean) * rs * g.w + b.w;
    *reinterpret_cast<float4*>(xout + (size_t)row * D + lane * 4) = o;
    if (write_next) {
        float vv[4] = {o.x, o.y, o.z, o.w};
        __nv_bfloat16 h[4], lo[4];
#pragma unroll
        for (int j = 0; j < 4; j++) {
            h[j] = __float2bfloat16(vv[j]);
            lo[j] = __float2bfloat16(vv[j] - __bfloat162float(h[j]));
        }
        size_t oo = (size_t)row * KTOT + 512 + lane * 4;
        *reinterpret_cast<uint2*>(&g_ah[oo]) = *reinterpret_cast<uint2*>(h);
        *reinterpret_cast<uint2*>(&g_al[oo]) = *reinterpret_cast<uint2*>(lo);
    }
}

// ---------------- host launcher ----------------
extern "C" void kernel_launch(void* const* d_in, const int* in_sizes, int n_in,
                              void* d_out, int out_size) {
    const float* x     = (const float*)d_in[0];
    const int*   ei    = (const int*)d_in[1];
    const int*   et    = (const int*)d_in[2];
    const float* W     = (const float*)d_in[3];
    const float* root  = (const float*)d_in[4];
    const float* bias  = (const float*)d_in[5];
    const float* gamma = (const float*)d_in[6];
    const float* beta  = (const float*)d_in[7];
    float* out = (float*)d_out;

    const int* src = ei;
    const int* dst = ei + N_EDGES;

    float *px1 = nullptr, *px2 = nullptr;
    cudaGetSymbolAddress((void**)&px1, g_x1);
    cudaGetSymbolAddress((void**)&px2, g_x2);

    cudaFuncSetAttribute(k_gemm, cudaFuncAttributeMaxDynamicSharedMemorySize, SMEM_DYN);

    // CSR build (edge structure is layer-invariant)
    k_zero_cnt<<<(NSEG + 255) / 256, 256>>>();
    k_hist<<<(N_EDGES + 255) / 256, 256>>>(dst, et);
    int nb = (NSEG + 1023) / 1024;
    k_scan1<<<nb, 1024>>>();
    k_scan2<<<1, 256>>>(nb);
    k_scan3<<<nb, 1024>>>();
    k_scatter<<<(N_EDGES + 255) / 256, 256>>>(src, dst, et);

    // weight transpose + split
    k_bprep<<<(NLAYER * D * KTOT + 255) / 256, 256>>>(W, root);
    // self-cols for layer 0
    k_convx<<<(N_NODES + 7) / 8, 256>>>(x);

    const float* xin = x;
    for (int l = 0; l < NLAYER; l++) {
        k_agg<<<(NSEG + 7) / 8, 256>>>(xin);
        k_gemm<<<NTILES, 256, SMEM_DYN>>>(l, bias + (size_t)l * D);
        float* xout = (l == NLAYER - 1) ? out : ((l == 0) ? px1 : px2);
        k_epi<<<(N_NODES + 7) / 8, 256>>>(xin, gamma + (size_t)l * D,
                                          beta + (size_t)l * D, xout,
                                          l < NLAYER - 1 ? 1 : 0);
        xin = xout;
    }
}